// round 1
// baseline (speedup 1.0000x reference)
#include <cuda_runtime.h>

// Retrace_9844065042706
// Inputs (metadata order):
//   0: Q                      [B,T,D] f32
//   1: expected_target_Q      [B,T,D] f32
//   2: target_Q               [B,T,D] f32
//   3: rewards                [B,T,D] f32
//   4: target_policy_probs    [B,T,D] f32
//   5: behaviour_policy_probs [B,T]   f32
// Output: scalar f32 = mean((Q[:, :-1] - Q_ret)^2)

#define RB 2048
#define RT 512
#define RD 16

static constexpr float GAMMA = 0.99f;

__global__ void zero_out_kernel(float* out) {
    if (threadIdx.x == 0) out[0] = 0.0f;
}

__global__ void __launch_bounds__(128)
retrace_kernel(const float* __restrict__ Q,
               const float* __restrict__ E,
               const float* __restrict__ TQ,
               const float* __restrict__ R,
               const float* __restrict__ TPP,
               const float* __restrict__ BPP,
               float* __restrict__ out)
{
    const int gid = blockIdx.x * blockDim.x + threadIdx.x;   // 0 .. B*D-1
    const int d = gid & (RD - 1);
    const int b = gid >> 4;

    const size_t base = (size_t)b * RT * RD + d;
    const size_t bb   = (size_t)b * RT;

    // carry = target_Q[b, T-1, d]
    float carry = TQ[base + (size_t)(RT - 1) * RD];
    float sum = 0.0f;

    #pragma unroll 4
    for (int t = RT - 1; t >= 1; --t) {
        const size_t i1 = base + (size_t)t * RD;   // index at time t
        const size_t i0 = i1 - RD;                 // index at time t-1

        const float e   = E[i1];
        const float tq  = TQ[i1];
        const float tpp = TPP[i1];
        const float bp  = BPP[bb + t];
        const float r   = R[i0];
        const float qv  = Q[i0];

        // c = exp(min(tpp - bp, 0))
        const float c = __expf(fminf(tpp - bp, 0.0f));

        // q = r + GAMMA * (e + c * (carry - tq))
        const float q = fmaf(GAMMA, fmaf(c, carry - tq, e), r);

        const float err = qv - q;
        sum = fmaf(err, err, sum);
        carry = q;
    }

    // warp reduce
    #pragma unroll
    for (int o = 16; o > 0; o >>= 1)
        sum += __shfl_down_sync(0xffffffffu, sum, o);

    __shared__ float ws[4];  // 128 threads = 4 warps
    const int lane = threadIdx.x & 31;
    const int w    = threadIdx.x >> 5;
    if (lane == 0) ws[w] = sum;
    __syncthreads();

    if (w == 0) {
        float v = (lane < 4) ? ws[lane] : 0.0f;
        #pragma unroll
        for (int o = 2; o > 0; o >>= 1)
            v += __shfl_down_sync(0xffffffffu, v, o);
        if (lane == 0) {
            const float invN = 1.0f / ((float)RB * (float)(RT - 1) * (float)RD);
            atomicAdd(out, v * invN);
        }
    }
}

extern "C" void kernel_launch(void* const* d_in, const int* in_sizes, int n_in,
                              void* d_out, int out_size)
{
    const float* Q   = (const float*)d_in[0];
    const float* E   = (const float*)d_in[1];
    const float* TQ  = (const float*)d_in[2];
    const float* R   = (const float*)d_in[3];
    const float* TPP = (const float*)d_in[4];
    const float* BPP = (const float*)d_in[5];
    float* out = (float*)d_out;

    zero_out_kernel<<<1, 32>>>(out);

    const int threads = 128;
    const int total   = RB * RD;            // 32768 chains
    const int blocks  = total / threads;    // 256 blocks
    retrace_kernel<<<blocks, threads>>>(Q, E, TQ, R, TPP, BPP, out);
}

// round 2
// speedup vs baseline: 2.8242x; 2.8242x over previous
#include <cuda_runtime.h>

// Retrace_9844065042706 — parallel affine-scan formulation.
// q_j = a_j + m_j * carry  (affine) => split T into SEG segments, scan each
// with symbolic carry, compose quadratic loss contributions in a 2nd pass.
//
// Inputs (metadata order):
//   0: Q [B,T,D]  1: expected_target_Q [B,T,D]  2: target_Q [B,T,D]
//   3: rewards [B,T,D]  4: target_policy_probs [B,T,D]
//   5: behaviour_policy_probs [B,T]
// Output: scalar f32 mean((Q[:, :-1] - Q_ret)^2)

#define RB 2048
#define RT 512
#define RD 16
#define SEG 8
#define NJ (RT - 1)        // 511 scan steps, j = 0..510
#define SEGLEN 64          // ceil(511/8); last segment has 63
#define BD (RB * RD)       // 32768 chains

static constexpr float GAMMA = 0.99f;

// Scratch: [SEG][B*D] layout so pass-2 reads are coalesced across bd.
__device__ float g_A[SEG * BD];
__device__ float g_M[SEG * BD];
__device__ float g_alpha[SEG * BD];
__device__ float g_beta[SEG * BD];
__device__ float g_delta[SEG * BD];

__global__ void zero_out_kernel(float* out) {
    if (threadIdx.x == 0) out[0] = 0.0f;
}

// ---------------------------------------------------------------------------
// Pass 1: one thread per (segment, b, d). Backward scan over the segment with
// symbolic incoming carry:  q_j = q0_j + P_j * carry_in.
// err_j = (Q_j - q0_j) - P_j * carry_in  =>  segment loss is quadratic in
// carry_in with coefficients (alpha, -2*beta, delta).
// ---------------------------------------------------------------------------
__global__ void __launch_bounds__(128)
retrace_pass1(const float* __restrict__ Q,
              const float* __restrict__ E,
              const float* __restrict__ TQ,
              const float* __restrict__ R,
              const float* __restrict__ TPP,
              const float* __restrict__ BPP)
{
    const int gid = blockIdx.x * blockDim.x + threadIdx.x;  // 0 .. SEG*BD-1
    const int bd  = gid & (BD - 1);
    const int s   = gid >> 15;          // BD = 2^15
    const int d   = bd & (RD - 1);
    const int b   = bd >> 4;

    const int lo = s * SEGLEN;
    const int hi = min(lo + SEGLEN, NJ);   // j in [lo, hi)

    const size_t base = (size_t)b * RT * RD + d;
    const size_t bb   = (size_t)b * RT;

    float q0 = 0.0f, P = 1.0f;
    float alpha = 0.0f, beta = 0.0f, delta = 0.0f;

    #pragma unroll 4
    for (int j = hi - 1; j >= lo; --j) {
        const int t = j + 1;
        const size_t i1 = base + (size_t)t * RD;  // time t
        const size_t i0 = i1 - RD;                // time j = t-1

        const float e   = E[i1];
        const float tq  = TQ[i1];
        const float tpp = TPP[i1];
        const float bp  = BPP[bb + t];
        const float r   = R[i0];
        const float qv  = Q[i0];

        const float c = __expf(fminf(tpp - bp, 0.0f));
        const float m = GAMMA * c;
        // a = r + GAMMA*(e - c*tq)
        const float a = fmaf(GAMMA, fmaf(-c, tq, e), r);

        // compose: q0 <- a + m*q0 ; P <- m*P
        q0 = fmaf(m, q0, a);
        P  = m * P;

        const float u = qv - q0;
        alpha = fmaf(u, u, alpha);
        beta  = fmaf(u, P, beta);
        delta = fmaf(P, P, delta);
    }

    const int idx = s * BD + bd;
    g_A[idx]     = q0;
    g_M[idx]     = P;
    g_alpha[idx] = alpha;
    g_beta[idx]  = beta;
    g_delta[idx] = delta;
}

// ---------------------------------------------------------------------------
// Pass 2: one thread per (b,d) chain. Propagate carry across segments from
// high j to low j, accumulate quadratic loss, reduce to scalar.
// ---------------------------------------------------------------------------
__global__ void __launch_bounds__(128)
retrace_pass2(const float* __restrict__ TQ, float* __restrict__ out)
{
    const int bd = blockIdx.x * blockDim.x + threadIdx.x;   // 0 .. BD-1
    const int d  = bd & (RD - 1);
    const int b  = bd >> 4;

    // initial carry = target_Q[b, T-1, d]
    float carry = TQ[(size_t)b * RT * RD + (size_t)(RT - 1) * RD + d];
    float sum = 0.0f;

    #pragma unroll
    for (int s = SEG - 1; s >= 0; --s) {
        const int idx = s * BD + bd;
        const float al = g_alpha[idx];
        const float be = g_beta[idx];
        const float de = g_delta[idx];
        const float A  = g_A[idx];
        const float M  = g_M[idx];

        // sum += al - 2*be*carry + de*carry^2
        sum += fmaf(carry, fmaf(de, carry, -2.0f * be), al);
        carry = fmaf(M, carry, A);
    }

    // warp reduce
    #pragma unroll
    for (int o = 16; o > 0; o >>= 1)
        sum += __shfl_down_sync(0xffffffffu, sum, o);

    __shared__ float ws[4];
    const int lane = threadIdx.x & 31;
    const int w    = threadIdx.x >> 5;
    if (lane == 0) ws[w] = sum;
    __syncthreads();

    if (w == 0) {
        float v = (lane < 4) ? ws[lane] : 0.0f;
        #pragma unroll
        for (int o = 2; o > 0; o >>= 1)
            v += __shfl_down_sync(0xffffffffu, v, o);
        if (lane == 0) {
            const float invN = 1.0f / ((float)RB * (float)NJ * (float)RD);
            atomicAdd(out, v * invN);
        }
    }
}

extern "C" void kernel_launch(void* const* d_in, const int* in_sizes, int n_in,
                              void* d_out, int out_size)
{
    const float* Q   = (const float*)d_in[0];
    const float* E   = (const float*)d_in[1];
    const float* TQ  = (const float*)d_in[2];
    const float* R   = (const float*)d_in[3];
    const float* TPP = (const float*)d_in[4];
    const float* BPP = (const float*)d_in[5];
    float* out = (float*)d_out;

    zero_out_kernel<<<1, 32>>>(out);

    // Pass 1: SEG*BD = 262144 threads
    retrace_pass1<<<(SEG * BD) / 128, 128>>>(Q, E, TQ, R, TPP, BPP);

    // Pass 2: BD = 32768 threads
    retrace_pass2<<<BD / 128, 128>>>(TQ, out);
}

// round 3
// speedup vs baseline: 2.8839x; 1.0212x over previous
#include <cuda_runtime.h>

// Retrace_9844065042706 — parallel affine-scan, float4-vectorized.
// q_j = a_j + m_j*carry (affine). T split into SEG segments; each segment
// scanned with symbolic carry, loss contribution is quadratic in carry_in.
//
// Inputs (metadata order):
//   0: Q [B,T,D]  1: expected_target_Q [B,T,D]  2: target_Q [B,T,D]
//   3: rewards [B,T,D]  4: target_policy_probs [B,T,D]
//   5: behaviour_policy_probs [B,T]
// Output: scalar f32 mean((Q[:, :-1] - Q_ret)^2)

#define RB 2048
#define RT 512
#define RD 16
#define SEG 16
#define NJ (RT - 1)          // 511 scan steps
#define SEGLEN 32            // ceil(511/16); last segment has 31
#define BD (RB * RD)         // 32768 chains

static constexpr float GAMMA = 0.99f;

// Scratch [SEG][BD], d-minor so pass-2 reads are coalesced. ~10 MB total,
// L2-resident between pass1 and pass2.
__device__ float g_A[SEG * BD];
__device__ float g_M[SEG * BD];
__device__ float g_alpha[SEG * BD];
__device__ float g_beta[SEG * BD];
__device__ float g_delta[SEG * BD];

// ---------------------------------------------------------------------------
// Pass 1: one thread per (segment, b, d-group-of-4). float4 loads.
// Backward scan with symbolic incoming carry: q = q0 + P*carry_in.
// Segment loss = alpha - 2*beta*carry_in + delta*carry_in^2.
// ---------------------------------------------------------------------------
__global__ void __launch_bounds__(128)
retrace_pass1(const float* __restrict__ Q,
              const float* __restrict__ E,
              const float* __restrict__ TQ,
              const float* __restrict__ R,
              const float* __restrict__ TPP,
              const float* __restrict__ BPP,
              float* __restrict__ out)
{
    const int gid = blockIdx.x * blockDim.x + threadIdx.x; // 0 .. SEG*BD/4-1
    if (gid == 0) out[0] = 0.0f;   // replaces separate zero kernel

    const int nchain4 = BD / 4;                 // 8192 float4-chains
    const int c4  = gid & (nchain4 - 1);        // which (b, d4)
    const int s   = gid >> 13;                  // segment
    const int d4  = c4 & 3;                     // d group (4 lanes)
    const int b   = c4 >> 2;

    const int lo = s * SEGLEN;
    const int hi = min(lo + SEGLEN, NJ);

    const size_t base = (size_t)b * RT * RD + d4 * 4;  // float index, 16B aligned
    const size_t bb   = (size_t)b * RT;

    float q0x = 0.f, q0y = 0.f, q0z = 0.f, q0w = 0.f;
    float Px = 1.f, Py = 1.f, Pz = 1.f, Pw = 1.f;
    float alx = 0.f, aly = 0.f, alz = 0.f, alw = 0.f;
    float bex = 0.f, bey = 0.f, bez = 0.f, bew = 0.f;
    float dex = 0.f, dey = 0.f, dez = 0.f, dew = 0.f;

    #pragma unroll 2
    for (int j = hi - 1; j >= lo; --j) {
        const int t = j + 1;
        const size_t i1 = base + (size_t)t * RD;
        const size_t i0 = i1 - RD;

        const float4 e   = *(const float4*)(E   + i1);
        const float4 tq  = *(const float4*)(TQ  + i1);
        const float4 tpp = *(const float4*)(TPP + i1);
        const float4 r   = *(const float4*)(R   + i0);
        const float4 qv  = *(const float4*)(Q   + i0);
        const float  bp  = BPP[bb + t];

        const float cx = __expf(fminf(tpp.x - bp, 0.f));
        const float cy = __expf(fminf(tpp.y - bp, 0.f));
        const float cz = __expf(fminf(tpp.z - bp, 0.f));
        const float cw = __expf(fminf(tpp.w - bp, 0.f));

        const float mx = GAMMA * cx, my = GAMMA * cy;
        const float mz = GAMMA * cz, mw = GAMMA * cw;

        const float ax = fmaf(GAMMA, fmaf(-cx, tq.x, e.x), r.x);
        const float ay = fmaf(GAMMA, fmaf(-cy, tq.y, e.y), r.y);
        const float az = fmaf(GAMMA, fmaf(-cz, tq.z, e.z), r.z);
        const float aw = fmaf(GAMMA, fmaf(-cw, tq.w, e.w), r.w);

        q0x = fmaf(mx, q0x, ax);  Px *= mx;
        q0y = fmaf(my, q0y, ay);  Py *= my;
        q0z = fmaf(mz, q0z, az);  Pz *= mz;
        q0w = fmaf(mw, q0w, aw);  Pw *= mw;

        const float ux = qv.x - q0x, uy = qv.y - q0y;
        const float uz = qv.z - q0z, uw = qv.w - q0w;

        alx = fmaf(ux, ux, alx);  bex = fmaf(ux, Px, bex);  dex = fmaf(Px, Px, dex);
        aly = fmaf(uy, uy, aly);  bey = fmaf(uy, Py, bey);  dey = fmaf(Py, Py, dey);
        alz = fmaf(uz, uz, alz);  bez = fmaf(uz, Pz, bez);  dez = fmaf(Pz, Pz, dez);
        alw = fmaf(uw, uw, alw);  bew = fmaf(uw, Pw, bew);  dew = fmaf(Pw, Pw, dew);
    }

    const int idx = s * BD + c4 * 4;   // float index into [SEG][BD] scratch
    *(float4*)(g_A     + idx) = make_float4(q0x, q0y, q0z, q0w);
    *(float4*)(g_M     + idx) = make_float4(Px,  Py,  Pz,  Pw);
    *(float4*)(g_alpha + idx) = make_float4(alx, aly, alz, alw);
    *(float4*)(g_beta  + idx) = make_float4(bex, bey, bez, bew);
    *(float4*)(g_delta + idx) = make_float4(dex, dey, dez, dew);
}

// ---------------------------------------------------------------------------
// Pass 2: one thread per (b,d) chain. Compose segments high->low, reduce.
// Scratch is L2-resident (10 MB).
// ---------------------------------------------------------------------------
__global__ void __launch_bounds__(128)
retrace_pass2(const float* __restrict__ TQ, float* __restrict__ out)
{
    const int bd = blockIdx.x * blockDim.x + threadIdx.x;
    const int d  = bd & (RD - 1);
    const int b  = bd >> 4;

    float carry = TQ[(size_t)b * RT * RD + (size_t)(RT - 1) * RD + d];
    float sum = 0.0f;

    #pragma unroll
    for (int s = SEG - 1; s >= 0; --s) {
        const int idx = s * BD + bd;
        const float al = g_alpha[idx];
        const float be = g_beta[idx];
        const float de = g_delta[idx];
        const float A  = g_A[idx];
        const float M  = g_M[idx];

        sum += fmaf(carry, fmaf(de, carry, -2.0f * be), al);
        carry = fmaf(M, carry, A);
    }

    #pragma unroll
    for (int o = 16; o > 0; o >>= 1)
        sum += __shfl_down_sync(0xffffffffu, sum, o);

    __shared__ float ws[4];
    const int lane = threadIdx.x & 31;
    const int w    = threadIdx.x >> 5;
    if (lane == 0) ws[w] = sum;
    __syncthreads();

    if (w == 0) {
        float v = (lane < 4) ? ws[lane] : 0.0f;
        #pragma unroll
        for (int o = 2; o > 0; o >>= 1)
            v += __shfl_down_sync(0xffffffffu, v, o);
        if (lane == 0) {
            const float invN = 1.0f / ((float)RB * (float)NJ * (float)RD);
            atomicAdd(out, v * invN);
        }
    }
}

extern "C" void kernel_launch(void* const* d_in, const int* in_sizes, int n_in,
                              void* d_out, int out_size)
{
    const float* Q   = (const float*)d_in[0];
    const float* E   = (const float*)d_in[1];
    const float* TQ  = (const float*)d_in[2];
    const float* R   = (const float*)d_in[3];
    const float* TPP = (const float*)d_in[4];
    const float* BPP = (const float*)d_in[5];
    float* out = (float*)d_out;

    // Pass 1: SEG*BD/4 = 131072 threads (float4 per thread)
    retrace_pass1<<<(SEG * BD / 4) / 128, 128>>>(Q, E, TQ, R, TPP, BPP, out);

    // Pass 2: BD = 32768 threads
    retrace_pass2<<<BD / 128, 128>>>(TQ, out);
}

// round 4
// speedup vs baseline: 2.9603x; 1.0265x over previous
#include <cuda_runtime.h>

// Retrace_9844065042706 — parallel affine-scan, float2/thread, streaming loads.
// q_j = a_j + m_j*carry (affine). T split into SEG segments; each scanned with
// symbolic carry; per-segment loss is quadratic in carry_in.

#define RB 2048
#define RT 512
#define RD 16
#define SEG 16
#define NJ (RT - 1)          // 511 scan steps
#define SEGLEN 32            // ceil(511/16); last segment has 31
#define BD (RB * RD)         // 32768 chains
#define NC2 (BD / 2)         // 16384 float2-chains

static constexpr float GAMMA = 0.99f;

// Scratch [SEG][BD], d-minor. ~10 MB; with .cs streaming loads on the inputs
// this should stay L2-resident for pass2.
__device__ float g_A[SEG * BD];
__device__ float g_M[SEG * BD];
__device__ float g_alpha[SEG * BD];
__device__ float g_beta[SEG * BD];
__device__ float g_delta[SEG * BD];

// ---------------------------------------------------------------------------
// Pass 1: one thread per (segment, b, d-pair). float2 loads, evict-first.
// ---------------------------------------------------------------------------
__global__ void __launch_bounds__(128, 10)
retrace_pass1(const float* __restrict__ Q,
              const float* __restrict__ E,
              const float* __restrict__ TQ,
              const float* __restrict__ R,
              const float* __restrict__ TPP,
              const float* __restrict__ BPP,
              float* __restrict__ out)
{
    const int gid = blockIdx.x * blockDim.x + threadIdx.x; // 0 .. SEG*NC2-1
    if (gid == 0) out[0] = 0.0f;

    const int c2 = gid & (NC2 - 1);     // which (b, d-pair)
    const int s  = gid >> 14;           // segment
    const int dp = c2 & 7;              // d pair index (0..7)
    const int b  = c2 >> 3;

    const int lo = s * SEGLEN;
    const int hi = min(lo + SEGLEN, NJ);

    const size_t base = (size_t)b * RT * RD + dp * 2;
    const size_t bb   = (size_t)b * RT;

    float q0x = 0.f, q0y = 0.f;
    float Px = 1.f, Py = 1.f;
    float alx = 0.f, aly = 0.f;
    float bex = 0.f, bey = 0.f;
    float dex = 0.f, dey = 0.f;

    #pragma unroll 4
    for (int j = hi - 1; j >= lo; --j) {
        const int t = j + 1;
        const size_t i1 = base + (size_t)t * RD;
        const size_t i0 = i1 - RD;

        const float2 e   = __ldcs((const float2*)(E   + i1));
        const float2 tq  = __ldcs((const float2*)(TQ  + i1));
        const float2 tpp = __ldcs((const float2*)(TPP + i1));
        const float2 r   = __ldcs((const float2*)(R   + i0));
        const float2 qv  = __ldcs((const float2*)(Q   + i0));
        const float  bp  = __ldcs(BPP + bb + t);

        const float cx = __expf(fminf(tpp.x - bp, 0.f));
        const float cy = __expf(fminf(tpp.y - bp, 0.f));

        const float mx = GAMMA * cx;
        const float my = GAMMA * cy;

        const float ax = fmaf(GAMMA, fmaf(-cx, tq.x, e.x), r.x);
        const float ay = fmaf(GAMMA, fmaf(-cy, tq.y, e.y), r.y);

        q0x = fmaf(mx, q0x, ax);  Px *= mx;
        q0y = fmaf(my, q0y, ay);  Py *= my;

        const float ux = qv.x - q0x;
        const float uy = qv.y - q0y;

        alx = fmaf(ux, ux, alx);  bex = fmaf(ux, Px, bex);  dex = fmaf(Px, Px, dex);
        aly = fmaf(uy, uy, aly);  bey = fmaf(uy, Py, bey);  dey = fmaf(Py, Py, dey);
    }

    const int idx = s * BD + c2 * 2;
    *(float2*)(g_A     + idx) = make_float2(q0x, q0y);
    *(float2*)(g_M     + idx) = make_float2(Px,  Py);
    *(float2*)(g_alpha + idx) = make_float2(alx, aly);
    *(float2*)(g_beta  + idx) = make_float2(bex, bey);
    *(float2*)(g_delta + idx) = make_float2(dex, dey);
}

// ---------------------------------------------------------------------------
// Pass 2: one thread per (b,d) chain. Fully unrolled so all 80 scratch loads
// can be batched; scratch should be L2-resident.
// ---------------------------------------------------------------------------
__global__ void __launch_bounds__(128)
retrace_pass2(const float* __restrict__ TQ, float* __restrict__ out)
{
    const int bd = blockIdx.x * blockDim.x + threadIdx.x;
    const int d  = bd & (RD - 1);
    const int b  = bd >> 4;

    float carry = TQ[(size_t)b * RT * RD + (size_t)(RT - 1) * RD + d];
    float sum = 0.0f;

    #pragma unroll
    for (int s = SEG - 1; s >= 0; --s) {
        const int idx = s * BD + bd;
        const float al = __ldg(g_alpha + idx);
        const float be = __ldg(g_beta  + idx);
        const float de = __ldg(g_delta + idx);
        const float A  = __ldg(g_A     + idx);
        const float M  = __ldg(g_M     + idx);

        sum += fmaf(carry, fmaf(de, carry, -2.0f * be), al);
        carry = fmaf(M, carry, A);
    }

    #pragma unroll
    for (int o = 16; o > 0; o >>= 1)
        sum += __shfl_down_sync(0xffffffffu, sum, o);

    __shared__ float ws[4];
    const int lane = threadIdx.x & 31;
    const int w    = threadIdx.x >> 5;
    if (lane == 0) ws[w] = sum;
    __syncthreads();

    if (w == 0) {
        float v = (lane < 4) ? ws[lane] : 0.0f;
        #pragma unroll
        for (int o = 2; o > 0; o >>= 1)
            v += __shfl_down_sync(0xffffffffu, v, o);
        if (lane == 0) {
            const float invN = 1.0f / ((float)RB * (float)NJ * (float)RD);
            atomicAdd(out, v * invN);
        }
    }
}

extern "C" void kernel_launch(void* const* d_in, const int* in_sizes, int n_in,
                              void* d_out, int out_size)
{
    const float* Q   = (const float*)d_in[0];
    const float* E   = (const float*)d_in[1];
    const float* TQ  = (const float*)d_in[2];
    const float* R   = (const float*)d_in[3];
    const float* TPP = (const float*)d_in[4];
    const float* BPP = (const float*)d_in[5];
    float* out = (float*)d_out;

    // Pass 1: SEG*NC2 = 262144 threads (float2 per thread)
    retrace_pass1<<<(SEG * NC2) / 128, 128>>>(Q, E, TQ, R, TPP, BPP, out);

    // Pass 2: BD = 32768 threads
    retrace_pass2<<<BD / 128, 128>>>(TQ, out);
}

// round 5
// speedup vs baseline: 3.5137x; 1.1869x over previous
#include <cuda_runtime.h>
#include <cstdint>

// Retrace_9844065042706 — affine-segment scan, cp.async smem staging.
// Pass1: block = 8 b-chains x 16 d over one 32-step segment. Tile staged to
// smem with dense 16B cp.async copies (full 128B lines in flight), scan reads
// smem. Per-segment loss is quadratic in incoming carry: (alpha,-2beta,delta),
// carry map (A, M). Pass2 composes 16 segments per chain and reduces.

#define RB 2048
#define RT 512
#define RD 16
#define SEG 16
#define SEGLEN 32
#define NJ (RT - 1)            // 511
#define BD (RB * RD)           // 32768 chains
#define NBL 8                  // b's per block
#define NTH 128                // threads per block (8 b x 16 d)

// smem layout (floats): 5 tensors [8][32][16] padded (+16 floats per b) then bp [8][33]
#define BSTR  528              // per-b stride = 32*16 + 16 (pad -> conflict-free)
#define TS    (NBL * BSTR)     // 4224 floats per tensor
#define BPOFF (5 * TS)         // 21120
#define BPSTR 33
#define SMEM_FLOATS (BPOFF + NBL * BPSTR)   // 21384
#define SMEM_BYTES  (SMEM_FLOATS * 4)       // 85536

static constexpr float GAMMA = 0.99f;

// AoS scratch: per (seg, chain): {A, M, alpha, beta, delta, pad,pad,pad} = 32B
__device__ float g_scr[(size_t)SEG * BD * 8];

__device__ __forceinline__ void cp16(uint32_t s, const void* g) {
    asm volatile("cp.async.cg.shared.global [%0], [%1], 16;" :: "r"(s), "l"(g));
}
__device__ __forceinline__ void cp4(uint32_t s, const void* g) {
    asm volatile("cp.async.ca.shared.global [%0], [%1], 4;" :: "r"(s), "l"(g));
}
__device__ __forceinline__ void cp_commit() {
    asm volatile("cp.async.commit_group;");
}
template <int N>
__device__ __forceinline__ void cp_wait() {
    asm volatile("cp.async.wait_group %0;" :: "n"(N));
}

__device__ __forceinline__ uint32_t smem_u32(const void* p) {
    return (uint32_t)__cvta_generic_to_shared(p);
}

// copy rows [k0, k0+16) of the tile (all 5 tensors + bp) for this block
__device__ __forceinline__ void copy_half(
    float* sm, int tid, int bg, int lo, int k0,
    const float* __restrict__ E, const float* __restrict__ TQ,
    const float* __restrict__ TPP, const float* __restrict__ R,
    const float* __restrict__ Q, const float* __restrict__ BPP)
{
    const uint32_t sbase = smem_u32(sm);
    // main: 5 tensors * 8 b * 16 rows * 4 chunks = 2560 16B-chunks
    #pragma unroll 5
    for (int i = tid; i < 2560; i += NTH) {
        const int tensor = i >> 9;          // /512
        const int rem    = i & 511;
        const int b      = rem >> 6;        // /64
        const int r2     = rem & 63;
        const int k      = k0 + (r2 >> 2);
        const int d4     = r2 & 3;

        const float* gp = (tensor == 0) ? E : (tensor == 1) ? TQ
                        : (tensor == 2) ? TPP : (tensor == 3) ? R : Q;
        // tensors 0-2 hold t = lo+1+k (clamp 511); tensors 3-4 hold t = lo+k
        const int t = (tensor < 3) ? min(lo + 1 + k, RT - 1) : (lo + k);

        const size_t goff = ((size_t)(bg * NBL + b) * RT + t) * RD + d4 * 4;
        const uint32_t soff = sbase + (uint32_t)(tensor * TS + b * BSTR + k * RD + d4 * 4) * 4u;
        cp16(soff, gp + goff);
    }
    // bp: 8 b * 16 rows, 4B each
    for (int i = tid; i < NBL * 16; i += NTH) {
        const int b = i >> 4;
        const int k = k0 + (i & 15);
        const int t = min(lo + 1 + k, RT - 1);
        const size_t goff = (size_t)(bg * NBL + b) * RT + t;
        const uint32_t soff = sbase + (uint32_t)(BPOFF + b * BPSTR + k) * 4u;
        cp4(soff, BPP + goff);
    }
    cp_commit();
}

__global__ void __launch_bounds__(NTH)
retrace_pass1(const float* __restrict__ Q,
              const float* __restrict__ E,
              const float* __restrict__ TQ,
              const float* __restrict__ TPP,
              const float* __restrict__ R,
              const float* __restrict__ BPP,
              float* __restrict__ out)
{
    extern __shared__ float sm[];
    const int tid = threadIdx.x;
    const int s   = blockIdx.x & (SEG - 1);
    const int bg  = blockIdx.x >> 4;           // b-group (0..255)

    if (blockIdx.x == 0 && tid == 0) out[0] = 0.0f;

    const int lo    = s * SEGLEN;
    const int steps = min(SEGLEN, NJ - lo);    // 32 or 31 (seg 15)

    // stage high half (rows 16..31, scanned first), then low half
    copy_half(sm, tid, bg, lo, 16, E, TQ, TPP, R, Q, BPP);
    copy_half(sm, tid, bg, lo, 0,  E, TQ, TPP, R, Q, BPP);

    const int b_l = tid >> 4;
    const int d   = tid & 15;
    const int rb  = b_l * BSTR + d;            // per-thread row base (floats)
    const int bpb = BPOFF + b_l * BPSTR;

    float q0 = 0.f, P = 1.f, al = 0.f, be = 0.f, de = 0.f;

    cp_wait<1>();            // high half resident
    __syncthreads();

    #pragma unroll 4
    for (int k = steps - 1; k >= 16; --k) {
        const int ro = rb + k * RD;
        const float e   = sm[ro];
        const float tq  = sm[TS + ro];
        const float tpp = sm[2 * TS + ro];
        const float r   = sm[3 * TS + ro];
        const float qv  = sm[4 * TS + ro];
        const float bp  = sm[bpb + k];

        const float c = __expf(fminf(tpp - bp, 0.f));
        const float m = GAMMA * c;
        const float a = fmaf(GAMMA, fmaf(-c, tq, e), r);
        q0 = fmaf(m, q0, a);  P *= m;
        const float u = qv - q0;
        al = fmaf(u, u, al);  be = fmaf(u, P, be);  de = fmaf(P, P, de);
    }

    cp_wait<0>();            // low half resident
    __syncthreads();

    #pragma unroll 4
    for (int k = 15; k >= 0; --k) {
        const int ro = rb + k * RD;
        const float e   = sm[ro];
        const float tq  = sm[TS + ro];
        const float tpp = sm[2 * TS + ro];
        const float r   = sm[3 * TS + ro];
        const float qv  = sm[4 * TS + ro];
        const float bp  = sm[bpb + k];

        const float c = __expf(fminf(tpp - bp, 0.f));
        const float m = GAMMA * c;
        const float a = fmaf(GAMMA, fmaf(-c, tq, e), r);
        q0 = fmaf(m, q0, a);  P *= m;
        const float u = qv - q0;
        al = fmaf(u, u, al);  be = fmaf(u, P, be);  de = fmaf(P, P, de);
    }

    const int chain = (bg * NBL + b_l) * RD + d;
    const size_t sl = ((size_t)s * BD + chain) * 8;
    *(float4*)(g_scr + sl) = make_float4(q0, P, al, be);
    g_scr[sl + 4] = de;
}

__global__ void __launch_bounds__(128)
retrace_pass2(const float* __restrict__ TQ, float* __restrict__ out)
{
    const int bd = blockIdx.x * blockDim.x + threadIdx.x;
    const int d  = bd & (RD - 1);
    const int b  = bd >> 4;

    float carry = TQ[(size_t)b * RT * RD + (size_t)(RT - 1) * RD + d];
    float sum = 0.0f;

    #pragma unroll
    for (int s = SEG - 1; s >= 0; --s) {
        const size_t sl = ((size_t)s * BD + bd) * 8;
        const float4 v = *(const float4*)(g_scr + sl);  // A, M, al, be
        const float dd = g_scr[sl + 4];
        sum += fmaf(carry, fmaf(dd, carry, -2.0f * v.w), v.z);
        carry = fmaf(v.y, carry, v.x);
    }

    #pragma unroll
    for (int o = 16; o > 0; o >>= 1)
        sum += __shfl_down_sync(0xffffffffu, sum, o);

    __shared__ float ws[4];
    const int lane = threadIdx.x & 31;
    const int w    = threadIdx.x >> 5;
    if (lane == 0) ws[w] = sum;
    __syncthreads();

    if (w == 0) {
        float v = (lane < 4) ? ws[lane] : 0.0f;
        #pragma unroll
        for (int o = 2; o > 0; o >>= 1)
            v += __shfl_down_sync(0xffffffffu, v, o);
        if (lane == 0) {
            const float invN = 1.0f / ((float)RB * (float)NJ * (float)RD);
            atomicAdd(out, v * invN);
        }
    }
}

extern "C" void kernel_launch(void* const* d_in, const int* in_sizes, int n_in,
                              void* d_out, int out_size)
{
    const float* Q   = (const float*)d_in[0];
    const float* E   = (const float*)d_in[1];
    const float* TQ  = (const float*)d_in[2];
    const float* R   = (const float*)d_in[3];
    const float* TPP = (const float*)d_in[4];
    const float* BPP = (const float*)d_in[5];
    float* out = (float*)d_out;

    static bool attr_done = false;
    if (!attr_done) {
        cudaFuncSetAttribute(retrace_pass1,
                             cudaFuncAttributeMaxDynamicSharedMemorySize,
                             SMEM_BYTES);
        attr_done = true;
    }

    // Pass 1: 256 b-groups x 16 segments = 4096 blocks
    retrace_pass1<<<(RB / NBL) * SEG, NTH, SMEM_BYTES>>>(Q, E, TQ, TPP, R, BPP, out);

    // Pass 2: BD = 32768 threads
    retrace_pass2<<<BD / 128, 128>>>(TQ, out);
}

// round 6
// speedup vs baseline: 3.7461x; 1.0662x over previous
#include <cuda_runtime.h>
#include <cstdint>

// Retrace_9844065042706 — affine-segment scan, cp.async smem staging.
// Pass1: block = 4 b-chains x 16 d over one 32-step segment (64 threads,
// 42.8KB smem -> 5 blocks/SM for copy/compute phase diversity).
// Pass2: one lane per (segment,chain); segment records composed by a
// 4-step shuffle tree (associative affine+quadratic composition).

#define RB 2048
#define RT 512
#define RD 16
#define SEG 16
#define SEGLEN 32
#define NJ (RT - 1)            // 511
#define BD (RB * RD)           // 32768 chains
#define NBL 4                  // b's per block
#define NTH 64                 // threads per block (4 b x 16 d)

// smem layout (floats): 5 tensors [4][32][16] padded (+16 per b), then bp [4][33]
#define BSTR  528              // per-b stride = 32*16 + 16 (conflict-free)
#define TS    (NBL * BSTR)     // 2112 floats per tensor
#define BPOFF (5 * TS)         // 10560
#define BPSTR 33
#define SMEM_FLOATS (BPOFF + NBL * BPSTR)   // 10692
#define SMEM_BYTES  (SMEM_FLOATS * 4)       // 42768 < 48KB default

static constexpr float GAMMA = 0.99f;

// AoS scratch: per (seg, chain): {A, M, alpha, beta, delta, pad*3} = 32B (1 sector)
__device__ float g_scr[(size_t)SEG * BD * 8];

__device__ __forceinline__ void cp16(uint32_t s, const void* g) {
    asm volatile("cp.async.cg.shared.global [%0], [%1], 16;" :: "r"(s), "l"(g));
}
__device__ __forceinline__ void cp4(uint32_t s, const void* g) {
    asm volatile("cp.async.ca.shared.global [%0], [%1], 4;" :: "r"(s), "l"(g));
}
__device__ __forceinline__ void cp_commit() {
    asm volatile("cp.async.commit_group;");
}
template <int N>
__device__ __forceinline__ void cp_wait() {
    asm volatile("cp.async.wait_group %0;" :: "n"(N));
}
__device__ __forceinline__ uint32_t smem_u32(const void* p) {
    return (uint32_t)__cvta_generic_to_shared(p);
}

// copy rows [k0, k0+16) of the tile (5 tensors + bp) for this block
__device__ __forceinline__ void copy_half(
    float* sm, int tid, int bg, int lo, int k0,
    const float* __restrict__ E, const float* __restrict__ TQ,
    const float* __restrict__ TPP, const float* __restrict__ R,
    const float* __restrict__ Q, const float* __restrict__ BPP)
{
    const uint32_t sbase = smem_u32(sm);
    // 5 tensors * 4 b * 16 rows * 4 chunks = 1280 16B-chunks
    #pragma unroll 5
    for (int i = tid; i < 1280; i += NTH) {
        const int tensor = i >> 8;          // /256
        const int rem    = i & 255;
        const int b      = rem >> 6;
        const int r2     = rem & 63;
        const int k      = k0 + (r2 >> 2);
        const int d4     = r2 & 3;

        const float* gp = (tensor == 0) ? E : (tensor == 1) ? TQ
                        : (tensor == 2) ? TPP : (tensor == 3) ? R : Q;
        // tensors 0-2 hold t = lo+1+k (clamp); tensors 3-4 hold t = lo+k
        const int t = (tensor < 3) ? min(lo + 1 + k, RT - 1) : (lo + k);

        const size_t goff = ((size_t)(bg * NBL + b) * RT + t) * RD + d4 * 4;
        const uint32_t soff = sbase + (uint32_t)(tensor * TS + b * BSTR + k * RD + d4 * 4) * 4u;
        cp16(soff, gp + goff);
    }
    // bp: 4 b * 16 rows
    {
        const int i = tid;                   // 64 threads cover 64 entries
        const int b = i >> 4;
        const int k = k0 + (i & 15);
        const int t = min(lo + 1 + k, RT - 1);
        const size_t goff = (size_t)(bg * NBL + b) * RT + t;
        const uint32_t soff = sbase + (uint32_t)(BPOFF + b * BPSTR + k) * 4u;
        cp4(soff, BPP + goff);
    }
    cp_commit();
}

__global__ void __launch_bounds__(NTH)
retrace_pass1(const float* __restrict__ Q,
              const float* __restrict__ E,
              const float* __restrict__ TQ,
              const float* __restrict__ TPP,
              const float* __restrict__ R,
              const float* __restrict__ BPP,
              float* __restrict__ out)
{
    extern __shared__ float sm[];
    const int tid = threadIdx.x;
    const int s   = blockIdx.x & (SEG - 1);
    const int bg  = blockIdx.x >> 4;           // b-group (0..511)

    if (blockIdx.x == 0 && tid == 0) out[0] = 0.0f;

    const int lo    = s * SEGLEN;
    const int steps = min(SEGLEN, NJ - lo);    // 32, or 31 for seg 15

    // stage high half (rows 16..31, scanned first), then low half
    copy_half(sm, tid, bg, lo, 16, E, TQ, TPP, R, Q, BPP);
    copy_half(sm, tid, bg, lo, 0,  E, TQ, TPP, R, Q, BPP);

    const int b_l = tid >> 4;
    const int d   = tid & 15;
    const int rb  = b_l * BSTR + d;
    const int bpb = BPOFF + b_l * BPSTR;

    float q0 = 0.f, P = 1.f, al = 0.f, be = 0.f, de = 0.f;

    cp_wait<1>();
    __syncthreads();

    #pragma unroll 4
    for (int k = steps - 1; k >= 16; --k) {
        const int ro = rb + k * RD;
        const float e   = sm[ro];
        const float tq  = sm[TS + ro];
        const float tpp = sm[2 * TS + ro];
        const float r   = sm[3 * TS + ro];
        const float qv  = sm[4 * TS + ro];
        const float bp  = sm[bpb + k];

        const float c = __expf(fminf(tpp - bp, 0.f));
        const float m = GAMMA * c;
        const float a = fmaf(GAMMA, fmaf(-c, tq, e), r);
        q0 = fmaf(m, q0, a);  P *= m;
        const float u = qv - q0;
        al = fmaf(u, u, al);  be = fmaf(u, P, be);  de = fmaf(P, P, de);
    }

    cp_wait<0>();
    __syncthreads();

    #pragma unroll 4
    for (int k = 15; k >= 0; --k) {
        const int ro = rb + k * RD;
        const float e   = sm[ro];
        const float tq  = sm[TS + ro];
        const float tpp = sm[2 * TS + ro];
        const float r   = sm[3 * TS + ro];
        const float qv  = sm[4 * TS + ro];
        const float bp  = sm[bpb + k];

        const float c = __expf(fminf(tpp - bp, 0.f));
        const float m = GAMMA * c;
        const float a = fmaf(GAMMA, fmaf(-c, tq, e), r);
        q0 = fmaf(m, q0, a);  P *= m;
        const float u = qv - q0;
        al = fmaf(u, u, al);  be = fmaf(u, P, be);  de = fmaf(P, P, de);
    }

    const int chain = (bg * NBL + b_l) * RD + d;
    const size_t sl = ((size_t)s * BD + chain) * 8;
    *(float4*)(g_scr + sl) = make_float4(q0, P, al, be);
    g_scr[sl + 4] = de;
}

// ---------------------------------------------------------------------------
// Pass 2: one lane per (segment, chain); 16 lanes/chain. Shuffle-tree compose.
// Composition (X = lower-j run, Y = higher-j run; carry flows Y -> X):
//   alpha'' = aY + aX - 2 bX AY + dX AY^2
//   beta''  = bY + bX MY - dX AY MY
//   delta'' = dY + dX MY^2
//   A'' = AX + MX AY ;  M'' = MX MY
// ---------------------------------------------------------------------------
__global__ void __launch_bounds__(128)
retrace_pass2(const float* __restrict__ TQ, float* __restrict__ out)
{
    const int gid   = blockIdx.x * blockDim.x + threadIdx.x; // 0..SEG*BD-1
    const int s     = gid & 15;                              // segment = lane16
    const int chain = gid >> 4;

    const size_t sl = ((size_t)s * BD + chain) * 8;
    const float4 v = *(const float4*)(g_scr + sl);   // A, M, al, be
    float A = v.x, M = v.y, al = v.z, be = v.w;
    float de = g_scr[sl + 4];

    #pragma unroll
    for (int k = 1; k < 16; k <<= 1) {
        const float oA  = __shfl_down_sync(0xffffffffu, A,  k, 16);
        const float oM  = __shfl_down_sync(0xffffffffu, M,  k, 16);
        const float oal = __shfl_down_sync(0xffffffffu, al, k, 16);
        const float obe = __shfl_down_sync(0xffffffffu, be, k, 16);
        const float ode = __shfl_down_sync(0xffffffffu, de, k, 16);

        const float nal = oal + al - 2.0f * be * oA + de * oA * oA;
        const float nbe = obe + (be - de * oA) * oM;
        const float nde = ode + de * oM * oM;
        const float nA  = fmaf(M, oA, A);
        const float nM  = M * oM;
        al = nal; be = nbe; de = nde; A = nA; M = nM;
    }

    float sum = 0.0f;
    if (s == 0) {
        const int b = chain >> 4;
        const int d = chain & 15;
        const float carry = TQ[((size_t)b * RT + (RT - 1)) * RD + d];
        sum = fmaf(carry, fmaf(de, carry, -2.0f * be), al);
    }

    // warp reduce (sum is nonzero on lanes 0 and 16 only)
    #pragma unroll
    for (int o = 16; o > 0; o >>= 1)
        sum += __shfl_down_sync(0xffffffffu, sum, o);

    __shared__ float ws[4];
    const int lane = threadIdx.x & 31;
    const int w    = threadIdx.x >> 5;
    if (lane == 0) ws[w] = sum;
    __syncthreads();

    if (w == 0) {
        float x = (lane < 4) ? ws[lane] : 0.0f;
        #pragma unroll
        for (int o = 2; o > 0; o >>= 1)
            x += __shfl_down_sync(0xffffffffu, x, o);
        if (lane == 0) {
            const float invN = 1.0f / ((float)RB * (float)NJ * (float)RD);
            atomicAdd(out, x * invN);
        }
    }
}

extern "C" void kernel_launch(void* const* d_in, const int* in_sizes, int n_in,
                              void* d_out, int out_size)
{
    const float* Q   = (const float*)d_in[0];
    const float* E   = (const float*)d_in[1];
    const float* TQ  = (const float*)d_in[2];
    const float* R   = (const float*)d_in[3];
    const float* TPP = (const float*)d_in[4];
    const float* BPP = (const float*)d_in[5];
    float* out = (float*)d_out;

    // Pass 1: 512 b-groups x 16 segments = 8192 blocks of 64 threads
    retrace_pass1<<<(RB / NBL) * SEG, NTH, SMEM_BYTES>>>(Q, E, TQ, TPP, R, BPP, out);

    // Pass 2: SEG*BD = 524288 threads
    retrace_pass2<<<(SEG * BD) / 128, 128>>>(TQ, out);
}